// round 16
// baseline (speedup 1.0000x reference)
#include <cuda_runtime.h>
#include <cuda_bf16.h>
#include <cstdint>

#define DD 128

// 51.2 MB scratch for support1 = X @ W1 (static device array: allowed, no alloc)
__device__ float g_s1[100000 * DD];

// ---------------------------------------------------------------------------
// TF32 helpers
// ---------------------------------------------------------------------------
__device__ __forceinline__ uint32_t cvt_tf32(float x) {
    uint32_t u;
    asm("cvt.rna.tf32.f32 %0, %1;" : "=r"(u) : "f"(x));
    return u;
}
__device__ __forceinline__ void split_tf32(float x, float& hi, float& lo) {
    uint32_t uh = cvt_tf32(x);
    hi = __uint_as_float(uh);
    lo = __uint_as_float(cvt_tf32(x - hi));
}

#define MMA_TF32(d, a, b)                                                     \
    asm volatile(                                                             \
        "mma.sync.aligned.m16n8k8.row.col.f32.tf32.tf32.f32 "                 \
        "{%0,%1,%2,%3},{%4,%5,%6,%7},{%8,%9},{%0,%1,%2,%3};"                  \
        : "+f"((d)[0]), "+f"((d)[1]), "+f"((d)[2]), "+f"((d)[3])              \
        : "r"((a)[0]), "r"((a)[1]), "r"((a)[2]), "r"((a)[3]),                 \
          "r"((b)[0]), "r"((b)[1]))

// smem: hi/lo packed as float2, single buffer (R12 structure)
#define XS2_STRIDE 36                 // 32 cols + 4 pad (float2 units)
#define WS2_STRIDE 132                // 128 cols + 4 pad
#define XS2_ELEMS (128 * XS2_STRIDE)  // 4608 float2
#define WS2_ELEMS (32 * WS2_STRIDE)   // 4224 float2
#define SMEM_BYTES ((XS2_ELEMS + WS2_ELEMS) * 8)   // 70656 B

// ---------------------------------------------------------------------------
// Single-matrix 3xTF32 GEMM, 128x128 tile/block, 8 warps.
// RED=0: dst[r] = acc (plain store; used for g_s1 = X@W1)
// RED=1: red.add acc into dst (out pre-filled with bias; used for X@W0)
// ---------------------------------------------------------------------------
template <int RED>
__global__ __launch_bounds__(256) void gemm_tf32_one(
    const float* __restrict__ X, const float* __restrict__ W,
    float* __restrict__ dst, int N)
{
    extern __shared__ float2 sm2[];
    float2* Xb = sm2;
    float2* Wb = Xb + XS2_ELEMS;

    const int tid   = threadIdx.x;
    const int lane  = tid & 31;
    const int gid   = lane >> 2;       // 0..7
    const int tig   = lane & 3;        // 0..3
    const int wid   = tid >> 5;
    const int rbase = (wid & 3) * 32;
    const int nbase = (wid >> 2) * 64;
    const int row0  = blockIdx.x * 128;

    float cd[2][8][4];
#pragma unroll
    for (int mt = 0; mt < 2; mt++)
#pragma unroll
        for (int nt = 0; nt < 8; nt++)
#pragma unroll
            for (int j = 0; j < 4; j++) cd[mt][nt][j] = 0.f;

    for (int kc = 0; kc < DD; kc += 32) {
        __syncthreads();
#pragma unroll
        for (int i = 0; i < 4; i++) {
            int idx = tid + i * 256;
            int r = idx >> 3;
            int q = idx & 7;
            int gr = row0 + r;
            if (gr >= N) gr = N - 1;
            float4 v = *(const float4*)&X[(size_t)gr * DD + kc + q * 4];
            float h0, l0, h1, l1, h2, l2, h3, l3;
            split_tf32(v.x, h0, l0); split_tf32(v.y, h1, l1);
            split_tf32(v.z, h2, l2); split_tf32(v.w, h3, l3);
            float2* p = Xb + r * XS2_STRIDE + q * 4;
            *(float4*)&p[0] = make_float4(h0, l0, h1, l1);
            *(float4*)&p[2] = make_float4(h2, l2, h3, l3);
        }
#pragma unroll
        for (int i = 0; i < 4; i++) {
            int idx = tid + i * 256;
            int r = idx >> 5;
            int q = idx & 31;
            float4 v = *(const float4*)&W[(size_t)(kc + r) * DD + q * 4];
            float h0, l0, h1, l1, h2, l2, h3, l3;
            split_tf32(v.x, h0, l0); split_tf32(v.y, h1, l1);
            split_tf32(v.z, h2, l2); split_tf32(v.w, h3, l3);
            float2* p = Wb + r * WS2_STRIDE + q * 4;
            *(float4*)&p[0] = make_float4(h0, l0, h1, l1);
            *(float4*)&p[2] = make_float4(h2, l2, h3, l3);
        }
        __syncthreads();

#pragma unroll
        for (int k8 = 0; k8 < 4; k8++) {
            const int kk = k8 * 8;
            float2 a2[2][4];
#pragma unroll
            for (int mt = 0; mt < 2; mt++) {
                int r = rbase + mt * 16 + gid;
                a2[mt][0] = Xb[r * XS2_STRIDE + kk + tig];
                a2[mt][1] = Xb[(r + 8) * XS2_STRIDE + kk + tig];
                a2[mt][2] = Xb[r * XS2_STRIDE + kk + tig + 4];
                a2[mt][3] = Xb[(r + 8) * XS2_STRIDE + kk + tig + 4];
            }
            uint32_t ah[2][4], al[2][4];
#pragma unroll
            for (int mt = 0; mt < 2; mt++)
#pragma unroll
                for (int j = 0; j < 4; j++) {
                    ah[mt][j] = __float_as_uint(a2[mt][j].x);
                    al[mt][j] = __float_as_uint(a2[mt][j].y);
                }
#pragma unroll
            for (int nt = 0; nt < 8; nt++) {
                int ncol = nbase + nt * 8 + gid;
                float2 b0 = Wb[(kk + tig) * WS2_STRIDE + ncol];
                float2 b1 = Wb[(kk + tig + 4) * WS2_STRIDE + ncol];
                uint32_t bh[2] = {__float_as_uint(b0.x), __float_as_uint(b1.x)};
                uint32_t bl[2] = {__float_as_uint(b0.y), __float_as_uint(b1.y)};
#pragma unroll
                for (int mt = 0; mt < 2; mt++) {
                    MMA_TF32(cd[mt][nt], ah[mt], bh);   // hi*hi
                    MMA_TF32(cd[mt][nt], ah[mt], bl);   // hi*lo
                    MMA_TF32(cd[mt][nt], al[mt], bh);   // lo*hi
                }
            }
        }
    }

#pragma unroll
    for (int nt = 0; nt < 8; nt++) {
        int col = nbase + nt * 8 + tig * 2;
#pragma unroll
        for (int mt = 0; mt < 2; mt++) {
            int r0 = row0 + rbase + mt * 16 + gid;
            int r1 = r0 + 8;
            if (r0 < N) {
                float* p = dst + (size_t)r0 * DD + col;
                if (RED == 0)
                    *(float2*)p = make_float2(cd[mt][nt][0], cd[mt][nt][1]);
                else
                    asm volatile("red.global.add.v2.f32 [%0], {%1,%2};"
                                 :: "l"(p), "f"(cd[mt][nt][0]),
                                    "f"(cd[mt][nt][1]) : "memory");
            }
            if (r1 < N) {
                float* p = dst + (size_t)r1 * DD + col;
                if (RED == 0)
                    *(float2*)p = make_float2(cd[mt][nt][2], cd[mt][nt][3]);
                else
                    asm volatile("red.global.add.v2.f32 [%0], {%1,%2};"
                                 :: "l"(p), "f"(cd[mt][nt][2]),
                                    "f"(cd[mt][nt][3]) : "memory");
            }
        }
    }
}

// ---------------------------------------------------------------------------
// fill: out[r][c] = bias[c] (float4 broadcast; stride keeps column fixed)
// ---------------------------------------------------------------------------
__global__ __launch_bounds__(256) void fill_bias_kernel(
    float* __restrict__ out, const float* __restrict__ bias, int N, int ZB)
{
    int tid = threadIdx.x;
    float4 bv = *(const float4*)&bias[(tid & 31) * 4];
    size_t total4 = (size_t)N * (DD / 4);
    for (size_t i = (size_t)blockIdx.x * 256 + tid; i < total4;
         i += (size_t)ZB * 256)
        ((float4*)out)[i] = bv;
}

// ---------------------------------------------------------------------------
// Edge aggregation (R8-proven): one warp per 32-edge batch, coalesced index
// loads, 4-deep gather->red pipeline, red.add.v4.f32 into out.
// ---------------------------------------------------------------------------
__global__ __launch_bounds__(256) void edge_kernel(
    const int* __restrict__ ei, const float* __restrict__ ev,
    float* __restrict__ out, int E)
{
    const int lane = threadIdx.x & 31;
    int wglob = blockIdx.x * 8 + (threadIdx.x >> 5);
    int e0 = wglob * 32;
    if (e0 >= E) return;

    int e = e0 + lane;
    bool valid = e < E;
    int src = valid ? __ldg(&ei[e]) : 0;
    int dst = valid ? __ldg(&ei[E + e]) : 0;
    float a = valid ? __ldg(&ev[e]) : 0.f;

    const unsigned FULL = 0xffffffffu;
#pragma unroll 1
    for (int j0 = 0; j0 < 32; j0 += 4) {
        float4 v[4];
        int d[4];
        float s[4];
#pragma unroll
        for (int jj = 0; jj < 4; jj++) {
            int j = j0 + jj;
            int sj = __shfl_sync(FULL, src, j);
            d[jj] = __shfl_sync(FULL, dst, j);
            s[jj] = __shfl_sync(FULL, a, j);
            v[jj] = *(const float4*)(g_s1 + (size_t)sj * DD + lane * 4);
        }
#pragma unroll
        for (int jj = 0; jj < 4; jj++) {
            float4 t = v[jj];
            float sc = s[jj];
            t.x *= sc; t.y *= sc; t.z *= sc; t.w *= sc;
            float* p = out + (size_t)d[jj] * DD + lane * 4;
            asm volatile("red.global.add.v4.f32 [%0], {%1,%2,%3,%4};"
                         :: "l"(p), "f"(t.x), "f"(t.y), "f"(t.z), "f"(t.w)
                         : "memory");
        }
    }
}

extern "C" void kernel_launch(void* const* d_in, const int* in_sizes, int n_in,
                              void* d_out, int out_size)
{
    const float* X    = (const float*)d_in[0];   // [N,128] f32
    const int*   ei   = (const int*)d_in[1];     // [2,E] int32
    const float* ev   = (const float*)d_in[2];   // [E] f32
    const float* W0   = (const float*)d_in[3];   // [128,128] f32
    const float* W1   = (const float*)d_in[4];   // [128,128] f32
    const float* bias = (const float*)d_in[5];   // [128] f32
    float* out = (float*)d_out;

    int N = in_sizes[0] / DD;
    int E = in_sizes[2];

    // One-time setup (first call is the correctness run, outside graph capture;
    // no device-memory allocation happens here — streams/events only).
    static cudaStream_t s1 = nullptr;
    static cudaEvent_t eFork = nullptr, eFill = nullptr, eW1 = nullptr,
                       eJoin = nullptr;
    static float* s1ptr = nullptr;
    if (s1 == nullptr) {
        cudaStreamCreateWithFlags(&s1, cudaStreamNonBlocking);
        cudaEventCreateWithFlags(&eFork, cudaEventDisableTiming);
        cudaEventCreateWithFlags(&eFill, cudaEventDisableTiming);
        cudaEventCreateWithFlags(&eW1, cudaEventDisableTiming);
        cudaEventCreateWithFlags(&eJoin, cudaEventDisableTiming);
        cudaGetSymbolAddress((void**)&s1ptr, g_s1);
        cudaFuncSetAttribute(gemm_tf32_one<0>,
                             cudaFuncAttributeMaxDynamicSharedMemorySize,
                             SMEM_BYTES);
        cudaFuncSetAttribute(gemm_tf32_one<1>,
                             cudaFuncAttributeMaxDynamicSharedMemorySize,
                             SMEM_BYTES);
    }

    int GX = (N + 127) / 128;                    // 782
    int EB = (E + 32 * 8 - 1) / (32 * 8);        // 6250
    int ZB = 512;

    // Fork side stream into the capture graph.
    cudaEventRecord(eFork, 0);
    cudaStreamWaitEvent(s1, eFork, 0);

    // stream1: out = bias (concurrent with gemmW1)
    fill_bias_kernel<<<ZB, 256, 0, s1>>>(out, bias, N, ZB);
    cudaEventRecord(eFill, s1);

    // stream0: g_s1 = X @ W1
    gemm_tf32_one<0><<<GX, 256, SMEM_BYTES>>>(X, W1, s1ptr, N);
    cudaEventRecord(eW1, 0);

    // stream0: edge scatter (needs g_s1 [program order] + bias fill)
    cudaStreamWaitEvent(0, eFill, 0);
    edge_kernel<<<EB, 256>>>(ei, ev, out, E);

    // stream1: out += X @ W0 (needs fill [program order]; deferred past W1 so
    // it overlaps the L2-bound edge kernel instead of the tensor-bound W1)
    cudaStreamWaitEvent(s1, eW1, 0);
    gemm_tf32_one<1><<<GX, 256, SMEM_BYTES, s1>>>(X, W0, out, N);
    cudaEventRecord(eJoin, s1);

    // join back to stream0
    cudaStreamWaitEvent(0, eJoin, 0);
}